// round 1
// baseline (speedup 1.0000x reference)
#include <cuda_runtime.h>
#include <cuda_bf16.h>
#include <mma.h>

using namespace nvcuda;

// ---------------- problem constants ----------------
constexpr int CB    = 32;     // batch
constexpr int CC    = 256;    // channels
constexpr int CHEADS= 8;
constexpr int CWS   = 8;      // window size
constexpr int CSS   = 4;      // shift
constexpr int CHID  = 1024;
constexpr int CN    = 64;     // tokens per window
constexpr int CHD   = 32;     // head dim
constexpr int MTOK  = CB * 64 * 64;  // 131072 tokens

// ---------------- device scratch (no allocations allowed) ----------------
__device__ __nv_bfloat16 g_hw  [(size_t)MTOK * CC];        // LN1+shift+partition out
__device__ __nv_bfloat16 g_qkv [(size_t)MTOK * 3 * CC];    // qkv gemm out
__device__ __nv_bfloat16 g_att [(size_t)MTOK * CC];        // attention out
__device__ float         g_proj[(size_t)MTOK * CC];        // proj gemm out (window order)
__device__ float         g_x1  [(size_t)MTOK * CC];        // residual stream after attn
__device__ __nv_bfloat16 g_ln2 [(size_t)MTOK * CC];        // LN2 out
__device__ __nv_bfloat16 g_g12 [(size_t)MTOK * 2 * CHID];  // fc12 gemm out
__device__ __nv_bfloat16 g_gat [(size_t)MTOK * CHID];      // silu(gate)*feat
__device__ __nv_bfloat16 g_wqkv [3 * CC * CC];
__device__ __nv_bfloat16 g_wproj[CC * CC];
__device__ __nv_bfloat16 g_wf12 [2 * CHID * CC];
__device__ __nv_bfloat16 g_wf2  [CC * CHID];

// ---------------- small helpers ----------------
__device__ __forceinline__ float warp_sum(float v) {
#pragma unroll
    for (int o = 16; o > 0; o >>= 1) v += __shfl_xor_sync(0xffffffffu, v, o);
    return v;
}
__device__ __forceinline__ int reg3(int p) { return p < 56 ? 0 : (p < 60 ? 1 : 2); }

// ---------------- weight fp32 -> bf16 ----------------
__global__ void k_f2bf(const float* __restrict__ in, __nv_bfloat16* __restrict__ out, int n) {
    int i = blockIdx.x * blockDim.x + threadIdx.x;
    if (i < n) out[i] = __float2bfloat16(in[i]);
}

// ---------------- LN1 + cyclic shift + window partition ----------------
// output row m (window order): b = m/4096, wi = (m/64)%64, n = m%64
// shifted coords (hs,ws) -> original ( (hs+SS)&63, (ws+SS)&63 )
__global__ void k_ln1_shift(const float* __restrict__ x, const float* __restrict__ w,
                            const float* __restrict__ bb, __nv_bfloat16* __restrict__ out) {
    int gw = (blockIdx.x * blockDim.x + threadIdx.x) >> 5;
    int lane = threadIdx.x & 31;
    if (gw >= MTOK) return;
    int b = gw >> 12, r = gw & 4095;
    int wi = r >> 6, n = r & 63;
    int hs = ((wi >> 3) << 3) + (n >> 3);
    int ws = ((wi & 7) << 3) + (n & 7);
    int h0 = (hs + CSS) & 63, w0 = (ws + CSS) & 63;
    const float4* row = (const float4*)(x + ((size_t)(b << 12) + (h0 << 6) + w0) * CC);
    float4 a = row[lane * 2], c = row[lane * 2 + 1];
    float s  = a.x + a.y + a.z + a.w + c.x + c.y + c.z + c.w;
    float sq = a.x*a.x + a.y*a.y + a.z*a.z + a.w*a.w + c.x*c.x + c.y*c.y + c.z*c.z + c.w*c.w;
    s = warp_sum(s); sq = warp_sum(sq);
    float mean = s * (1.f / 256.f);
    float var  = sq * (1.f / 256.f) - mean * mean;
    float rs   = rsqrtf(var + 1e-5f);
    const float4* wp = (const float4*)w;
    const float4* bp = (const float4*)bb;
    float4 w0v = wp[lane * 2], w1v = wp[lane * 2 + 1];
    float4 b0v = bp[lane * 2], b1v = bp[lane * 2 + 1];
    __align__(16) __nv_bfloat16 o8[8];
    o8[0] = __float2bfloat16((a.x - mean) * rs * w0v.x + b0v.x);
    o8[1] = __float2bfloat16((a.y - mean) * rs * w0v.y + b0v.y);
    o8[2] = __float2bfloat16((a.z - mean) * rs * w0v.z + b0v.z);
    o8[3] = __float2bfloat16((a.w - mean) * rs * w0v.w + b0v.w);
    o8[4] = __float2bfloat16((c.x - mean) * rs * w1v.x + b1v.x);
    o8[5] = __float2bfloat16((c.y - mean) * rs * w1v.y + b1v.y);
    o8[6] = __float2bfloat16((c.z - mean) * rs * w1v.z + b1v.z);
    o8[7] = __float2bfloat16((c.w - mean) * rs * w1v.w + b1v.w);
    *(uint4*)(out + (size_t)gw * CC + lane * 8) = *(const uint4*)o8;
}

// ---------------- generic bf16 GEMM: C[M,N] = A[M,K] @ W[N,K]^T + bias (+resid) ----------------
// BM=128, BN=64, BK=32, 8 warps (4x2), warp tile 32x32 (2x2 wmma)
template <typename OutT, bool RES>
__global__ void __launch_bounds__(256)
k_gemm(const __nv_bfloat16* __restrict__ A, const __nv_bfloat16* __restrict__ W,
       const float* __restrict__ bias, OutT* __restrict__ C,
       const float* __restrict__ resid, int M, int N, int K) {
    __shared__ __align__(128) char smem[36864];
    __nv_bfloat16* sA = (__nv_bfloat16*)smem;            // 128 x 48 (pad)
    __nv_bfloat16* sB = (__nv_bfloat16*)(smem + 12288);  // 64 x 48
    float* sC = (float*)smem;                             // 128 x 72 (reuses smem)

    const int tid  = threadIdx.x;
    const int warp = tid >> 5;
    const int wm   = warp & 3;  // 0..3 -> 32-row chunks
    const int wn   = warp >> 2; // 0..1 -> 32-col chunks
    const int m0 = blockIdx.y << 7;
    const int n0 = blockIdx.x << 6;

    wmma::fragment<wmma::accumulator, 16, 16, 16, float> acc[2][2];
#pragma unroll
    for (int i = 0; i < 2; i++)
#pragma unroll
        for (int j = 0; j < 2; j++) wmma::fill_fragment(acc[i][j], 0.f);

    for (int k0 = 0; k0 < K; k0 += 32) {
        // stage A tile 128x32 (512 x 16B)
#pragma unroll
        for (int v = tid; v < 512; v += 256) {
            int row = v >> 2, cv = (v & 3) << 3;
            *(uint4*)(sA + row * 48 + cv) =
                *(const uint4*)(A + (size_t)(m0 + row) * K + k0 + cv);
        }
        // stage B tile 64x32 (256 x 16B)
        {
            int row = tid >> 2, cv = (tid & 3) << 3;
            *(uint4*)(sB + row * 48 + cv) =
                *(const uint4*)(W + (size_t)(n0 + row) * K + k0 + cv);
        }
        __syncthreads();
#pragma unroll
        for (int kk = 0; kk < 32; kk += 16) {
            wmma::fragment<wmma::matrix_a, 16, 16, 16, __nv_bfloat16, wmma::row_major> af[2];
            wmma::fragment<wmma::matrix_b, 16, 16, 16, __nv_bfloat16, wmma::col_major> bf[2];
            wmma::load_matrix_sync(af[0], sA + (wm * 32) * 48 + kk, 48);
            wmma::load_matrix_sync(af[1], sA + (wm * 32 + 16) * 48 + kk, 48);
            wmma::load_matrix_sync(bf[0], sB + (wn * 32) * 48 + kk, 48);
            wmma::load_matrix_sync(bf[1], sB + (wn * 32 + 16) * 48 + kk, 48);
#pragma unroll
            for (int i = 0; i < 2; i++)
#pragma unroll
                for (int j = 0; j < 2; j++)
                    wmma::mma_sync(acc[i][j], af[i], bf[j], acc[i][j]);
        }
        __syncthreads();
    }

#pragma unroll
    for (int i = 0; i < 2; i++)
#pragma unroll
        for (int j = 0; j < 2; j++)
            wmma::store_matrix_sync(sC + (wm * 32 + i * 16) * 72 + wn * 32 + j * 16,
                                    acc[i][j], 72, wmma::mem_row_major);
    __syncthreads();

#pragma unroll
    for (int it = 0; it < 32; it++) {
        int idx = it * 256 + tid;
        int r = idx >> 6, c = idx & 63;
        float v = sC[r * 72 + c] + bias[n0 + c];
        size_t gi = (size_t)(m0 + r) * N + n0 + c;
        if (RES) v += resid[gi];
        C[gi] = (OutT)v;
    }
}

// ---------------- attention: one block per (head, window), 64 threads ----------------
__global__ void __launch_bounds__(64)
k_attn(const __nv_bfloat16* __restrict__ qkv, const float* __restrict__ rpb,
       __nv_bfloat16* __restrict__ out) {
    const int h   = blockIdx.x;
    const int win = blockIdx.y;
    const int i   = threadIdx.x;
    __shared__ float ks[64][32];
    __shared__ float vs[64][32];
    __shared__ float bias_s[225];

    const __nv_bfloat16* base = qkv + (size_t)win * 64 * 768;
    // k,v row i -> shared (fp32)
    {
        const uint4* kp = (const uint4*)(base + i * 768 + 256 + h * 32);
        const uint4* vp = (const uint4*)(base + i * 768 + 512 + h * 32);
#pragma unroll
        for (int c = 0; c < 4; c++) {
            uint4 kv = kp[c], vv = vp[c];
            const __nv_bfloat162* kp2 = (const __nv_bfloat162*)&kv;
            const __nv_bfloat162* vp2 = (const __nv_bfloat162*)&vv;
#pragma unroll
            for (int e = 0; e < 4; e++) {
                float2 fk = __bfloat1622float2(kp2[e]);
                float2 fv = __bfloat1622float2(vp2[e]);
                ks[i][c * 8 + e * 2]     = fk.x;
                ks[i][c * 8 + e * 2 + 1] = fk.y;
                vs[i][c * 8 + e * 2]     = fv.x;
                vs[i][c * 8 + e * 2 + 1] = fv.y;
            }
        }
    }
    for (int t = i; t < 225; t += 64) bias_s[t] = rpb[t * 8 + h];

    float q[32];
    {
        const uint4* qp = (const uint4*)(base + i * 768 + h * 32);
        const float scale = 0.17677669529663687f; // 1/sqrt(32)
#pragma unroll
        for (int c = 0; c < 4; c++) {
            uint4 qv = qp[c];
            const __nv_bfloat162* q2 = (const __nv_bfloat162*)&qv;
#pragma unroll
            for (int e = 0; e < 4; e++) {
                float2 f = __bfloat1622float2(q2[e]);
                q[c * 8 + e * 2]     = f.x * scale;
                q[c * 8 + e * 2 + 1] = f.y * scale;
            }
        }
    }
    __syncthreads();

    const int wi = win & 63;
    const int wr = (wi >> 3) << 3, wc = (wi & 7) << 3;
    const int ri = i >> 3, ci = i & 7;
    const int myid = reg3(wr + ri) * 3 + reg3(wc + ci);

    float s[64];
    float mx = -1e30f;
#pragma unroll 4
    for (int j = 0; j < 64; j++) {
        const float4* kr = (const float4*)ks[j];
        float acc = 0.f;
#pragma unroll
        for (int d4 = 0; d4 < 8; d4++) {
            float4 k4 = kr[d4];
            acc += q[d4 * 4 + 0] * k4.x + q[d4 * 4 + 1] * k4.y +
                   q[d4 * 4 + 2] * k4.z + q[d4 * 4 + 3] * k4.w;
        }
        int rj = j >> 3, cj = j & 7;
        acc += bias_s[(ri - rj + 7) * 15 + (ci - cj + 7)];
        int jid = reg3(wr + rj) * 3 + reg3(wc + cj);
        if (jid != myid) acc -= 100.f;
        s[j] = acc;
        mx = fmaxf(mx, acc);
    }
    float sum = 0.f;
#pragma unroll
    for (int j = 0; j < 64; j++) { s[j] = __expf(s[j] - mx); sum += s[j]; }
    float inv = __frcp_rn(sum);

    float o[32];
#pragma unroll
    for (int d = 0; d < 32; d++) o[d] = 0.f;
#pragma unroll 4
    for (int j = 0; j < 64; j++) {
        float p = s[j] * inv;
        const float4* vr = (const float4*)vs[j];
#pragma unroll
        for (int d4 = 0; d4 < 8; d4++) {
            float4 v4 = vr[d4];
            o[d4 * 4 + 0] += p * v4.x;
            o[d4 * 4 + 1] += p * v4.y;
            o[d4 * 4 + 2] += p * v4.z;
            o[d4 * 4 + 3] += p * v4.w;
        }
    }
    __align__(16) __nv_bfloat16 ob[32];
#pragma unroll
    for (int d = 0; d < 32; d++) ob[d] = __float2bfloat16(o[d]);
    uint4* op = (uint4*)(out + (size_t)(win * 64 + i) * 256 + h * 32);
    const uint4* ob4 = (const uint4*)ob;
#pragma unroll
    for (int c = 0; c < 4; c++) op[c] = ob4[c];
}

// ---------------- residual (window-reverse + unshift) + LN2 ----------------
__global__ void k_resid_ln2(const float* __restrict__ x, const float* __restrict__ proj,
                            const float* __restrict__ w, const float* __restrict__ bb,
                            float* __restrict__ x1, __nv_bfloat16* __restrict__ ln2) {
    int gw = (blockIdx.x * blockDim.x + threadIdx.x) >> 5;
    int lane = threadIdx.x & 31;
    if (gw >= MTOK) return;
    int b = gw >> 12, pos = gw & 4095;
    int hh = pos >> 6, ww = pos & 63;
    int hs = (hh - CSS) & 63, ws = (ww - CSS) & 63;
    int m = (b << 12) + ((((hs >> 3) << 3) + (ws >> 3)) << 6) + ((hs & 7) << 3) + (ws & 7);
    const float4* xr = (const float4*)(x + (size_t)gw * CC);
    const float4* pr = (const float4*)(proj + (size_t)m * CC);
    float4 a = xr[lane * 2], c = xr[lane * 2 + 1];
    float4 p0 = pr[lane * 2], p1 = pr[lane * 2 + 1];
    a.x += p0.x; a.y += p0.y; a.z += p0.z; a.w += p0.w;
    c.x += p1.x; c.y += p1.y; c.z += p1.z; c.w += p1.w;
    float s  = a.x + a.y + a.z + a.w + c.x + c.y + c.z + c.w;
    float sq = a.x*a.x + a.y*a.y + a.z*a.z + a.w*a.w + c.x*c.x + c.y*c.y + c.z*c.z + c.w*c.w;
    s = warp_sum(s); sq = warp_sum(sq);
    float mean = s * (1.f / 256.f);
    float var  = sq * (1.f / 256.f) - mean * mean;
    float rs   = rsqrtf(var + 1e-5f);
    float4* x1r = (float4*)(x1 + (size_t)gw * CC);
    x1r[lane * 2] = a; x1r[lane * 2 + 1] = c;
    const float4* wp = (const float4*)w;
    const float4* bp = (const float4*)bb;
    float4 w0v = wp[lane * 2], w1v = wp[lane * 2 + 1];
    float4 b0v = bp[lane * 2], b1v = bp[lane * 2 + 1];
    __align__(16) __nv_bfloat16 o8[8];
    o8[0] = __float2bfloat16((a.x - mean) * rs * w0v.x + b0v.x);
    o8[1] = __float2bfloat16((a.y - mean) * rs * w0v.y + b0v.y);
    o8[2] = __float2bfloat16((a.z - mean) * rs * w0v.z + b0v.z);
    o8[3] = __float2bfloat16((a.w - mean) * rs * w0v.w + b0v.w);
    o8[4] = __float2bfloat16((c.x - mean) * rs * w1v.x + b1v.x);
    o8[5] = __float2bfloat16((c.y - mean) * rs * w1v.y + b1v.y);
    o8[6] = __float2bfloat16((c.z - mean) * rs * w1v.z + b1v.z);
    o8[7] = __float2bfloat16((c.w - mean) * rs * w1v.w + b1v.w);
    *(uint4*)(ln2 + (size_t)gw * CC + lane * 8) = *(const uint4*)o8;
}

// ---------------- SiLU gating: out[t,j] = silu(g[t,j]) * g[t,j+1024] ----------------
__global__ void k_gate(const __nv_bfloat16* __restrict__ g, __nv_bfloat16* __restrict__ out) {
    size_t idx = (size_t)blockIdx.x * blockDim.x + threadIdx.x; // one per 8 outputs
    if (idx >= (size_t)MTOK * 128) return;
    size_t t = idx >> 7;
    int c8 = (int)(idx & 127) << 3;
    const __nv_bfloat16* gr = g + t * 2048;
    uint4 gu = *(const uint4*)(gr + c8);
    uint4 fu = *(const uint4*)(gr + 1024 + c8);
    const __nv_bfloat162* g2 = (const __nv_bfloat162*)&gu;
    const __nv_bfloat162* f2 = (const __nv_bfloat162*)&fu;
    __align__(16) __nv_bfloat16 o8[8];
#pragma unroll
    for (int e = 0; e < 4; e++) {
        float2 gg = __bfloat1622float2(g2[e]);
        float2 ff = __bfloat1622float2(f2[e]);
        float s0 = gg.x / (1.f + __expf(-gg.x));
        float s1 = gg.y / (1.f + __expf(-gg.y));
        o8[e * 2]     = __float2bfloat16(s0 * ff.x);
        o8[e * 2 + 1] = __float2bfloat16(s1 * ff.y);
    }
    *(uint4*)(out + t * 1024 + c8) = *(const uint4*)o8;
}

// ---------------- launcher ----------------
extern "C" void kernel_launch(void* const* d_in, const int* in_sizes, int n_in,
                              void* d_out, int out_size) {
    const float* x     = (const float*)d_in[0];
    const float* n1w   = (const float*)d_in[1];
    const float* n1b   = (const float*)d_in[2];
    const float* qkvw  = (const float*)d_in[3];
    const float* qkvb  = (const float*)d_in[4];
    const float* projw = (const float*)d_in[5];
    const float* projb = (const float*)d_in[6];
    const float* rpb   = (const float*)d_in[7];
    const float* n2w   = (const float*)d_in[8];
    const float* n2b   = (const float*)d_in[9];
    const float* f12w  = (const float*)d_in[10];
    const float* f12b  = (const float*)d_in[11];
    const float* f2w   = (const float*)d_in[12];
    const float* f2b   = (const float*)d_in[13];
    float* out = (float*)d_out;

    void *p_hw, *p_qkv, *p_att, *p_proj, *p_x1, *p_ln2, *p_g12, *p_gat;
    void *p_wq, *p_wp, *p_w12, *p_w2;
    cudaGetSymbolAddress(&p_hw, g_hw);
    cudaGetSymbolAddress(&p_qkv, g_qkv);
    cudaGetSymbolAddress(&p_att, g_att);
    cudaGetSymbolAddress(&p_proj, g_proj);
    cudaGetSymbolAddress(&p_x1, g_x1);
    cudaGetSymbolAddress(&p_ln2, g_ln2);
    cudaGetSymbolAddress(&p_g12, g_g12);
    cudaGetSymbolAddress(&p_gat, g_gat);
    cudaGetSymbolAddress(&p_wq, g_wqkv);
    cudaGetSymbolAddress(&p_wp, g_wproj);
    cudaGetSymbolAddress(&p_w12, g_wf12);
    cudaGetSymbolAddress(&p_w2, g_wf2);

    // weights -> bf16
    k_f2bf<<<(196608 + 255) / 256, 256>>>(qkvw, (__nv_bfloat16*)p_wq, 196608);
    k_f2bf<<<(65536 + 255) / 256, 256>>>(projw, (__nv_bfloat16*)p_wp, 65536);
    k_f2bf<<<(524288 + 255) / 256, 256>>>(f12w, (__nv_bfloat16*)p_w12, 524288);
    k_f2bf<<<(262144 + 255) / 256, 256>>>(f2w, (__nv_bfloat16*)p_w2, 262144);

    // LN1 + shift + window partition
    k_ln1_shift<<<16384, 256>>>(x, n1w, n1b, (__nv_bfloat16*)p_hw);

    // qkv gemm: [131072,256] x [768,256]^T -> bf16
    k_gemm<__nv_bfloat16, false><<<dim3(12, 1024), 256>>>(
        (const __nv_bfloat16*)p_hw, (const __nv_bfloat16*)p_wq, qkvb,
        (__nv_bfloat16*)p_qkv, nullptr, MTOK, 768, 256);

    // windowed attention
    k_attn<<<dim3(8, 2048), 64>>>((const __nv_bfloat16*)p_qkv, rpb, (__nv_bfloat16*)p_att);

    // proj gemm: -> fp32 (window order)
    k_gemm<float, false><<<dim3(4, 1024), 256>>>(
        (const __nv_bfloat16*)p_att, (const __nv_bfloat16*)p_wp, projb,
        (float*)p_proj, nullptr, MTOK, 256, 256);

    // residual (window reverse + unshift) + LN2
    k_resid_ln2<<<16384, 256>>>(x, (const float*)p_proj, n2w, n2b,
                                (float*)p_x1, (__nv_bfloat16*)p_ln2);

    // fc12 gemm: [131072,256] x [2048,256]^T -> bf16
    k_gemm<__nv_bfloat16, false><<<dim3(32, 1024), 256>>>(
        (const __nv_bfloat16*)p_ln2, (const __nv_bfloat16*)p_w12, f12b,
        (__nv_bfloat16*)p_g12, nullptr, MTOK, 2048, 256);

    // SiLU gating
    k_gate<<<65536, 256>>>((const __nv_bfloat16*)p_g12, (__nv_bfloat16*)p_gat);

    // fc2 gemm: [131072,1024] x [256,1024]^T + x1 residual -> d_out (fp32)
    k_gemm<float, true><<<dim3(4, 1024), 256>>>(
        (const __nv_bfloat16*)p_gat, (const __nv_bfloat16*)p_w2, f2b,
        out, (const float*)p_x1, MTOK, 256, 1024);
}

// round 3
// speedup vs baseline: 1.4700x; 1.4700x over previous
#include <cuda_runtime.h>
#include <cuda_bf16.h>
#include <mma.h>

using namespace nvcuda;

// ---------------- problem constants ----------------
constexpr int CC    = 256;    // channels
constexpr int CSS   = 4;      // shift
constexpr int CHID  = 1024;
constexpr int MTOK  = 32 * 64 * 64;  // 131072 tokens

// ---------------- device scratch (no allocations allowed) ----------------
__device__ __nv_bfloat16 g_hw  [(size_t)MTOK * CC];        // LN1+shift+partition out
__device__ __nv_bfloat16 g_qkv [(size_t)MTOK * 3 * CC];    // qkv gemm out
__device__ __nv_bfloat16 g_att [(size_t)MTOK * CC];        // attention out
__device__ float         g_proj[(size_t)MTOK * CC];        // proj gemm out (window order)
__device__ float         g_x1  [(size_t)MTOK * CC];        // residual stream after attn
__device__ __nv_bfloat16 g_ln2 [(size_t)MTOK * CC];        // LN2 out
__device__ __nv_bfloat16 g_gat [(size_t)MTOK * CHID];      // silu(gate)*feat
__device__ __nv_bfloat16 g_wqkv [3 * CC * CC];
__device__ __nv_bfloat16 g_wproj[CC * CC];
__device__ __nv_bfloat16 g_wf12r[2 * CHID * CC];           // reordered (gate/feat interleaved)
__device__ float         g_b12r [2 * CHID];                // reordered fc12 bias
__device__ __nv_bfloat16 g_wf2  [CC * CHID];

// ---------------- small helpers ----------------
__device__ __forceinline__ float warp_sum(float v) {
#pragma unroll
    for (int o = 16; o > 0; o >>= 1) v += __shfl_xor_sync(0xffffffffu, v, o);
    return v;
}
__device__ __forceinline__ int reg3(int p) { return p < 56 ? 0 : (p < 60 ? 1 : 2); }

__device__ __forceinline__ void cp_async16(void* smem_dst, const void* gmem_src) {
    unsigned s = (unsigned)__cvta_generic_to_shared(smem_dst);
    asm volatile("cp.async.cg.shared.global [%0], [%1], 16;\n" :: "r"(s), "l"(gmem_src));
}
#define CP_COMMIT() asm volatile("cp.async.commit_group;\n" ::: "memory")
#define CP_WAIT2()  asm volatile("cp.async.wait_group 2;\n" ::: "memory")
#define CP_WAIT0()  asm volatile("cp.async.wait_group 0;\n" ::: "memory")

// ---------------- weight fp32 -> bf16 ----------------
__global__ void k_f2bf(const float* __restrict__ in, __nv_bfloat16* __restrict__ out, int n) {
    int i = blockIdx.x * blockDim.x + threadIdx.x;
    if (i < n) out[i] = __float2bfloat16(in[i]);
}

// fc12 weight+bias reorder: out row 2j = gate row j, out row 2j+1 = feat row j (=j+1024)
__global__ void k_w12r(const float* __restrict__ w, const float* __restrict__ b,
                       __nv_bfloat16* __restrict__ wr, float* __restrict__ br) {
    int i = blockIdx.x * blockDim.x + threadIdx.x;
    if (i < 2048 * 256) {
        int r = i >> 8, c = i & 255;
        int src = (r & 1) ? (r >> 1) + 1024 : (r >> 1);
        wr[i] = __float2bfloat16(w[src * 256 + c]);
    }
    if (i < 2048) {
        int src = (i & 1) ? (i >> 1) + 1024 : (i >> 1);
        br[i] = b[src];
    }
}

// ---------------- LN1 + cyclic shift + window partition ----------------
__global__ void k_ln1_shift(const float* __restrict__ x, const float* __restrict__ w,
                            const float* __restrict__ bb, __nv_bfloat16* __restrict__ out) {
    int gw = (blockIdx.x * blockDim.x + threadIdx.x) >> 5;
    int lane = threadIdx.x & 31;
    if (gw >= MTOK) return;
    int b = gw >> 12, r = gw & 4095;
    int wi = r >> 6, n = r & 63;
    int hs = ((wi >> 3) << 3) + (n >> 3);
    int ws = ((wi & 7) << 3) + (n & 7);
    int h0 = (hs + CSS) & 63, w0 = (ws + CSS) & 63;
    const float4* row = (const float4*)(x + ((size_t)(b << 12) + (h0 << 6) + w0) * CC);
    float4 a = row[lane * 2], c = row[lane * 2 + 1];
    float s  = a.x + a.y + a.z + a.w + c.x + c.y + c.z + c.w;
    float sq = a.x*a.x + a.y*a.y + a.z*a.z + a.w*a.w + c.x*c.x + c.y*c.y + c.z*c.z + c.w*c.w;
    s = warp_sum(s); sq = warp_sum(sq);
    float mean = s * (1.f / 256.f);
    float var  = sq * (1.f / 256.f) - mean * mean;
    float rs   = rsqrtf(var + 1e-5f);
    const float4* wp = (const float4*)w;
    const float4* bp = (const float4*)bb;
    float4 w0v = wp[lane * 2], w1v = wp[lane * 2 + 1];
    float4 b0v = bp[lane * 2], b1v = bp[lane * 2 + 1];
    __align__(16) __nv_bfloat16 o8[8];
    o8[0] = __float2bfloat16((a.x - mean) * rs * w0v.x + b0v.x);
    o8[1] = __float2bfloat16((a.y - mean) * rs * w0v.y + b0v.y);
    o8[2] = __float2bfloat16((a.z - mean) * rs * w0v.z + b0v.z);
    o8[3] = __float2bfloat16((a.w - mean) * rs * w0v.w + b0v.w);
    o8[4] = __float2bfloat16((c.x - mean) * rs * w1v.x + b1v.x);
    o8[5] = __float2bfloat16((c.y - mean) * rs * w1v.y + b1v.y);
    o8[6] = __float2bfloat16((c.z - mean) * rs * w1v.z + b1v.z);
    o8[7] = __float2bfloat16((c.w - mean) * rs * w1v.w + b1v.w);
    *(uint4*)(out + (size_t)gw * CC + lane * 8) = *(const uint4*)o8;
}

// ---------------- multistage pipelined bf16 GEMM ----------------
// C[M,N] = A[M,K] @ W[N,K]^T + bias, epilogue variants:
//   EPI=0: plain (OutT out)
//   EPI=1: + resid (float out)
//   EPI=2: gated pairs -> bf16 out, N_out = N/2
// BM=128, BN=128, BK=32, 4 stages, 8 warps (2m x 4n), warp tile 64x32
constexpr int GLDA = 40;                 // smem row stride (elems): conflict-free ldmatrix
constexpr int GSTG = 128 * GLDA;         // elems per matrix per stage (5120)
constexpr int GSMEM_BYTES = 8 * GSTG * 2; // 4 stages x (A+B) = 81920 B

__device__ __forceinline__ void stage_load(
    const __nv_bfloat16* __restrict__ A, const __nv_bfloat16* __restrict__ W,
    __nv_bfloat16* sm, int st, int kt, int m0, int n0, int K, int tid) {
    int k0 = kt << 5;
#pragma unroll
    for (int u = 0; u < 2; u++) {
        int ch = tid + (u << 8);
        int row = ch >> 2, c = (ch & 3) << 3;
        cp_async16(sm + st * GSTG + row * GLDA + c,
                   A + (size_t)(m0 + row) * K + k0 + c);
    }
#pragma unroll
    for (int u = 0; u < 2; u++) {
        int ch = tid + (u << 8);
        int row = ch >> 2, c = (ch & 3) << 3;
        cp_async16(sm + 4 * GSTG + st * GSTG + row * GLDA + c,
                   W + (size_t)(n0 + row) * K + k0 + c);
    }
}

template <int EPI, typename OutT>
__global__ void __launch_bounds__(256, 2)
k_gemm2(const __nv_bfloat16* __restrict__ A, const __nv_bfloat16* __restrict__ W,
        const float* __restrict__ bias, OutT* __restrict__ C,
        const float* __restrict__ resid, int M, int N, int K) {
    extern __shared__ __align__(16) char dsm[];
    __nv_bfloat16* sm = (__nv_bfloat16*)dsm;
    float* sC = (float*)dsm;                    // epilogue: 128 x 136 fp32

    const int tid  = threadIdx.x;
    const int warp = tid >> 5;
    const int wm   = warp >> 2;  // 0..1 -> 64-row chunk
    const int wn   = warp & 3;   // 0..3 -> 32-col chunk
    const int m0 = blockIdx.y << 7;
    const int n0 = blockIdx.x << 7;
    const int KT = K >> 5;

    wmma::fragment<wmma::accumulator, 16, 16, 16, float> acc[4][2];
#pragma unroll
    for (int i = 0; i < 4; i++)
#pragma unroll
        for (int j = 0; j < 2; j++) wmma::fill_fragment(acc[i][j], 0.f);

    // prologue: fill 3 stages
#pragma unroll
    for (int st = 0; st < 3; st++) { stage_load(A, W, sm, st, st, m0, n0, K, tid); CP_COMMIT(); }

    for (int kt = 0; kt < KT; kt++) {
        CP_WAIT2();
        __syncthreads();
        int nk = kt + 3;
        if (nk < KT) stage_load(A, W, sm, nk & 3, nk, m0, n0, K, tid);
        CP_COMMIT();

        const __nv_bfloat16* aS = sm + (kt & 3) * GSTG;
        const __nv_bfloat16* bS = sm + 4 * GSTG + (kt & 3) * GSTG;
#pragma unroll
        for (int kk = 0; kk < 32; kk += 16) {
            wmma::fragment<wmma::matrix_a, 16, 16, 16, __nv_bfloat16, wmma::row_major> af[4];
            wmma::fragment<wmma::matrix_b, 16, 16, 16, __nv_bfloat16, wmma::col_major> bf[2];
#pragma unroll
            for (int i = 0; i < 4; i++)
                wmma::load_matrix_sync(af[i], aS + (wm * 64 + i * 16) * GLDA + kk, GLDA);
#pragma unroll
            for (int j = 0; j < 2; j++)
                wmma::load_matrix_sync(bf[j], bS + (wn * 32 + j * 16) * GLDA + kk, GLDA);
#pragma unroll
            for (int i = 0; i < 4; i++)
#pragma unroll
                for (int j = 0; j < 2; j++)
                    wmma::mma_sync(acc[i][j], af[i], bf[j], acc[i][j]);
        }
        __syncthreads();
    }

    CP_WAIT0();
    __syncthreads();
#pragma unroll
    for (int i = 0; i < 4; i++)
#pragma unroll
        for (int j = 0; j < 2; j++)
            wmma::store_matrix_sync(sC + (wm * 64 + i * 16) * 136 + wn * 32 + j * 16,
                                    acc[i][j], 136, wmma::mem_row_major);
    __syncthreads();

    if (EPI == 2) {
        // gated: pairs (even=gate, odd=feat) -> bf16, out width N/2
#pragma unroll
        for (int it = 0; it < 8; it++) {
            int idx = it * 256 + tid;           // 2048 = 128 rows x 16 quads
            int r = idx >> 4, co4 = (idx & 15) << 2;
            int ci = co4 << 1;
            float4 u0 = *(float4*)(sC + r * 136 + ci);
            float4 u1 = *(float4*)(sC + r * 136 + ci + 4);
            float4 b0 = *(const float4*)(bias + n0 + ci);
            float4 b1 = *(const float4*)(bias + n0 + ci + 4);
            float gt[4] = {u0.x + b0.x, u0.z + b0.z, u1.x + b1.x, u1.z + b1.z};
            float ft[4] = {u0.y + b0.y, u0.w + b0.w, u1.y + b1.y, u1.w + b1.w};
            __align__(8) __nv_bfloat16 o4[4];
#pragma unroll
            for (int e = 0; e < 4; e++) {
                float s = gt[e] / (1.f + __expf(-gt[e]));
                o4[e] = __float2bfloat16(s * ft[e]);
            }
            *(uint2*)((__nv_bfloat16*)C + (size_t)(m0 + r) * (N >> 1) + (n0 >> 1) + co4) =
                *(const uint2*)o4;
        }
    } else {
#pragma unroll
        for (int it = 0; it < 16; it++) {
            int idx = it * 256 + tid;           // 4096 = 128 rows x 32 quads
            int r = idx >> 5, c4 = (idx & 31) << 2;
            float4 v = *(float4*)(sC + r * 136 + c4);
            float4 bv = *(const float4*)(bias + n0 + c4);
            v.x += bv.x; v.y += bv.y; v.z += bv.z; v.w += bv.w;
            size_t gi = (size_t)(m0 + r) * N + n0 + c4;
            if (EPI == 1) {
                float4 rv = *(const float4*)(resid + gi);
                v.x += rv.x; v.y += rv.y; v.z += rv.z; v.w += rv.w;
            }
            if (sizeof(OutT) == 4) {
                *(float4*)((float*)C + gi) = v;
            } else {
                __align__(8) __nv_bfloat16 o4[4];
                o4[0] = __float2bfloat16(v.x); o4[1] = __float2bfloat16(v.y);
                o4[2] = __float2bfloat16(v.z); o4[3] = __float2bfloat16(v.w);
                *(uint2*)((__nv_bfloat16*)C + gi) = *(const uint2*)o4;
            }
        }
    }
}

// ---------------- attention: one block per (head, window), 64 threads ----------------
__global__ void __launch_bounds__(64)
k_attn(const __nv_bfloat16* __restrict__ qkv, const float* __restrict__ rpb,
       __nv_bfloat16* __restrict__ out) {
    const int h   = blockIdx.x;
    const int win = blockIdx.y;
    const int i   = threadIdx.x;
    __shared__ float ks[64][32];
    __shared__ float vs[64][32];
    __shared__ float bias_s[225];

    const __nv_bfloat16* base = qkv + (size_t)win * 64 * 768;
    {
        const uint4* kp = (const uint4*)(base + i * 768 + 256 + h * 32);
        const uint4* vp = (const uint4*)(base + i * 768 + 512 + h * 32);
#pragma unroll
        for (int c = 0; c < 4; c++) {
            uint4 kv = kp[c], vv = vp[c];
            const __nv_bfloat162* kp2 = (const __nv_bfloat162*)&kv;
            const __nv_bfloat162* vp2 = (const __nv_bfloat162*)&vv;
#pragma unroll
            for (int e = 0; e < 4; e++) {
                float2 fk = __bfloat1622float2(kp2[e]);
                float2 fv = __bfloat1622float2(vp2[e]);
                ks[i][c * 8 + e * 2]     = fk.x;
                ks[i][c * 8 + e * 2 + 1] = fk.y;
                vs[i][c * 8 + e * 2]     = fv.x;
                vs[i][c * 8 + e * 2 + 1] = fv.y;
            }
        }
    }
    for (int t = i; t < 225; t += 64) bias_s[t] = rpb[t * 8 + h];

    float q[32];
    {
        const uint4* qp = (const uint4*)(base + i * 768 + h * 32);
        const float scale = 0.17677669529663687f;
#pragma unroll
        for (int c = 0; c < 4; c++) {
            uint4 qv = qp[c];
            const __nv_bfloat162* q2 = (const __nv_bfloat162*)&qv;
#pragma unroll
            for (int e = 0; e < 4; e++) {
                float2 f = __bfloat1622float2(q2[e]);
                q[c * 8 + e * 2]     = f.x * scale;
                q[c * 8 + e * 2 + 1] = f.y * scale;
            }
        }
    }
    __syncthreads();

    const int wi = win & 63;
    const int wr = (wi >> 3) << 3, wc = (wi & 7) << 3;
    const int ri = i >> 3, ci = i & 7;
    const int myid = reg3(wr + ri) * 3 + reg3(wc + ci);

    float s[64];
    float mx = -1e30f;
#pragma unroll 4
    for (int j = 0; j < 64; j++) {
        const float4* kr = (const float4*)ks[j];
        float acc = 0.f;
#pragma unroll
        for (int d4 = 0; d4 < 8; d4++) {
            float4 k4 = kr[d4];
            acc += q[d4 * 4 + 0] * k4.x + q[d4 * 4 + 1] * k4.y +
                   q[d4 * 4 + 2] * k4.z + q[d4 * 4 + 3] * k4.w;
        }
        int rj = j >> 3, cj = j & 7;
        acc += bias_s[(ri - rj + 7) * 15 + (ci - cj + 7)];
        int jid = reg3(wr + rj) * 3 + reg3(wc + cj);
        if (jid != myid) acc -= 100.f;
        s[j] = acc;
        mx = fmaxf(mx, acc);
    }
    float sum = 0.f;
#pragma unroll
    for (int j = 0; j < 64; j++) { s[j] = __expf(s[j] - mx); sum += s[j]; }
    float inv = __frcp_rn(sum);

    float o[32];
#pragma unroll
    for (int d = 0; d < 32; d++) o[d] = 0.f;
#pragma unroll 4
    for (int j = 0; j < 64; j++) {
        float p = s[j] * inv;
        const float4* vr = (const float4*)vs[j];
#pragma unroll
        for (int d4 = 0; d4 < 8; d4++) {
            float4 v4 = vr[d4];
            o[d4 * 4 + 0] += p * v4.x;
            o[d4 * 4 + 1] += p * v4.y;
            o[d4 * 4 + 2] += p * v4.z;
            o[d4 * 4 + 3] += p * v4.w;
        }
    }
    __align__(16) __nv_bfloat16 ob[32];
#pragma unroll
    for (int d = 0; d < 32; d++) ob[d] = __float2bfloat16(o[d]);
    uint4* op = (uint4*)(out + (size_t)(win * 64 + i) * 256 + h * 32);
    const uint4* ob4 = (const uint4*)ob;
#pragma unroll
    for (int c = 0; c < 4; c++) op[c] = ob4[c];
}

// ---------------- residual (window-reverse + unshift) + LN2 ----------------
__global__ void k_resid_ln2(const float* __restrict__ x, const float* __restrict__ proj,
                            const float* __restrict__ w, const float* __restrict__ bb,
                            float* __restrict__ x1, __nv_bfloat16* __restrict__ ln2) {
    int gw = (blockIdx.x * blockDim.x + threadIdx.x) >> 5;
    int lane = threadIdx.x & 31;
    if (gw >= MTOK) return;
    int b = gw >> 12, pos = gw & 4095;
    int hh = pos >> 6, ww = pos & 63;
    int hs = (hh - CSS) & 63, ws = (ww - CSS) & 63;
    int m = (b << 12) + ((((hs >> 3) << 3) + (ws >> 3)) << 6) + ((hs & 7) << 3) + (ws & 7);
    const float4* xr = (const float4*)(x + (size_t)gw * CC);
    const float4* pr = (const float4*)(proj + (size_t)m * CC);
    float4 a = xr[lane * 2], c = xr[lane * 2 + 1];
    float4 p0 = pr[lane * 2], p1 = pr[lane * 2 + 1];
    a.x += p0.x; a.y += p0.y; a.z += p0.z; a.w += p0.w;
    c.x += p1.x; c.y += p1.y; c.z += p1.z; c.w += p1.w;
    float s  = a.x + a.y + a.z + a.w + c.x + c.y + c.z + c.w;
    float sq = a.x*a.x + a.y*a.y + a.z*a.z + a.w*a.w + c.x*c.x + c.y*c.y + c.z*c.z + c.w*c.w;
    s = warp_sum(s); sq = warp_sum(sq);
    float mean = s * (1.f / 256.f);
    float var  = sq * (1.f / 256.f) - mean * mean;
    float rs   = rsqrtf(var + 1e-5f);
    float4* x1r = (float4*)(x1 + (size_t)gw * CC);
    x1r[lane * 2] = a; x1r[lane * 2 + 1] = c;
    const float4* wp = (const float4*)w;
    const float4* bp = (const float4*)bb;
    float4 w0v = wp[lane * 2], w1v = wp[lane * 2 + 1];
    float4 b0v = bp[lane * 2], b1v = bp[lane * 2 + 1];
    __align__(16) __nv_bfloat16 o8[8];
    o8[0] = __float2bfloat16((a.x - mean) * rs * w0v.x + b0v.x);
    o8[1] = __float2bfloat16((a.y - mean) * rs * w0v.y + b0v.y);
    o8[2] = __float2bfloat16((a.z - mean) * rs * w0v.z + b0v.z);
    o8[3] = __float2bfloat16((a.w - mean) * rs * w0v.w + b0v.w);
    o8[4] = __float2bfloat16((c.x - mean) * rs * w1v.x + b1v.x);
    o8[5] = __float2bfloat16((c.y - mean) * rs * w1v.y + b1v.y);
    o8[6] = __float2bfloat16((c.z - mean) * rs * w1v.z + b1v.z);
    o8[7] = __float2bfloat16((c.w - mean) * rs * w1v.w + b1v.w);
    *(uint4*)(ln2 + (size_t)gw * CC + lane * 8) = *(const uint4*)o8;
}

// ---------------- launcher ----------------
extern "C" void kernel_launch(void* const* d_in, const int* in_sizes, int n_in,
                              void* d_out, int out_size) {
    const float* x     = (const float*)d_in[0];
    const float* n1w   = (const float*)d_in[1];
    const float* n1b   = (const float*)d_in[2];
    const float* qkvw  = (const float*)d_in[3];
    const float* qkvb  = (const float*)d_in[4];
    const float* projw = (const float*)d_in[5];
    const float* projb = (const float*)d_in[6];
    const float* rpb   = (const float*)d_in[7];
    const float* n2w   = (const float*)d_in[8];
    const float* n2b   = (const float*)d_in[9];
    const float* f12w  = (const float*)d_in[10];
    const float* f12b  = (const float*)d_in[11];
    const float* f2w   = (const float*)d_in[12];
    const float* f2b   = (const float*)d_in[13];
    float* out = (float*)d_out;

    void *p_hw, *p_qkv, *p_att, *p_proj, *p_x1, *p_ln2, *p_gat;
    void *p_wq, *p_wp, *p_w12, *p_b12, *p_w2;
    cudaGetSymbolAddress(&p_hw, g_hw);
    cudaGetSymbolAddress(&p_qkv, g_qkv);
    cudaGetSymbolAddress(&p_att, g_att);
    cudaGetSymbolAddress(&p_proj, g_proj);
    cudaGetSymbolAddress(&p_x1, g_x1);
    cudaGetSymbolAddress(&p_ln2, g_ln2);
    cudaGetSymbolAddress(&p_gat, g_gat);
    cudaGetSymbolAddress(&p_wq, g_wqkv);
    cudaGetSymbolAddress(&p_wp, g_wproj);
    cudaGetSymbolAddress(&p_w12, g_wf12r);
    cudaGetSymbolAddress(&p_b12, g_b12r);
    cudaGetSymbolAddress(&p_w2, g_wf2);

    // idempotent, no static guard (deterministic per-call behavior)
    cudaFuncSetAttribute(k_gemm2<0, __nv_bfloat16>,
                         cudaFuncAttributeMaxDynamicSharedMemorySize, GSMEM_BYTES);
    cudaFuncSetAttribute(k_gemm2<1, float>,
                         cudaFuncAttributeMaxDynamicSharedMemorySize, GSMEM_BYTES);
    cudaFuncSetAttribute(k_gemm2<2, __nv_bfloat16>,
                         cudaFuncAttributeMaxDynamicSharedMemorySize, GSMEM_BYTES);
    cudaFuncSetAttribute(k_gemm2<0, float>,
                         cudaFuncAttributeMaxDynamicSharedMemorySize, GSMEM_BYTES);

    // weights -> bf16 (+ fc12 reorder)
    k_f2bf<<<(196608 + 255) / 256, 256>>>(qkvw, (__nv_bfloat16*)p_wq, 196608);
    k_f2bf<<<(65536 + 255) / 256, 256>>>(projw, (__nv_bfloat16*)p_wp, 65536);
    k_w12r<<<(524288 + 255) / 256, 256>>>(f12w, f12b, (__nv_bfloat16*)p_w12, (float*)p_b12);
    k_f2bf<<<(262144 + 255) / 256, 256>>>(f2w, (__nv_bfloat16*)p_w2, 262144);

    // LN1 + shift + window partition
    k_ln1_shift<<<16384, 256>>>(x, n1w, n1b, (__nv_bfloat16*)p_hw);

    // qkv gemm: [131072,256] x [768,256]^T -> bf16
    k_gemm2<0, __nv_bfloat16><<<dim3(6, 1024), 256, GSMEM_BYTES>>>(
        (const __nv_bfloat16*)p_hw, (const __nv_bfloat16*)p_wq, qkvb,
        (__nv_bfloat16*)p_qkv, nullptr, MTOK, 768, 256);

    // windowed attention
    k_attn<<<dim3(8, 2048), 64>>>((const __nv_bfloat16*)p_qkv, rpb, (__nv_bfloat16*)p_att);

    // proj gemm -> fp32 (window order)
    k_gemm2<0, float><<<dim3(2, 1024), 256, GSMEM_BYTES>>>(
        (const __nv_bfloat16*)p_att, (const __nv_bfloat16*)p_wp, projb,
        (float*)p_proj, nullptr, MTOK, 256, 256);

    // residual (window reverse + unshift) + LN2
    k_resid_ln2<<<16384, 256>>>(x, (const float*)p_proj, n2w, n2b,
                                (float*)p_x1, (__nv_bfloat16*)p_ln2);

    // fc12 gemm with fused SiLU-gate epilogue: [131072,256] x [2048,256]^T -> [131072,1024] bf16
    k_gemm2<2, __nv_bfloat16><<<dim3(16, 1024), 256, GSMEM_BYTES>>>(
        (const __nv_bfloat16*)p_ln2, (const __nv_bfloat16*)p_w12, (const float*)p_b12,
        (__nv_bfloat16*)p_gat, nullptr, MTOK, 2048, 256);

    // fc2 gemm: [131072,1024] x [256,1024]^T + x1 residual -> d_out (fp32)
    k_gemm2<1, float><<<dim3(2, 1024), 256, GSMEM_BYTES>>>(
        (const __nv_bfloat16*)p_gat, (const __nv_bfloat16*)p_w2, f2b,
        out, (const float*)p_x1, MTOK, 256, 1024);
}